// round 5
// baseline (speedup 1.0000x reference)
#include <cuda_runtime.h>
#include <stdint.h>
#include <math.h>

#define HEADS 16
#define DH    64
#define BATCH 8
#define SEQ   512
#define DMODEL 1024
#define INNER 1024            // HEADS*DH
#define QKV_N 3072            // 3*INNER
#define NTOK  4096            // BATCH*SEQ

// Scratch (device globals: allocation-free, graph-capture safe)
__device__ float g_qkv[(size_t)NTOK * QKV_N];               // 48 MB
__device__ float g_dots[(size_t)BATCH * HEADS * SEQ * SEQ]; // 128 MB
__device__ float g_av[(size_t)NTOK * INNER];                // 16 MB

// ---------------------------------------------------------------------------
__device__ __forceinline__ uint32_t f2tf32(float x) {
    uint32_t u;
    asm("cvt.rna.tf32.f32 %0, %1;" : "=r"(u) : "f"(x));
    return u;
}

__device__ __forceinline__ void mma8(float* c, const uint32_t* a, const uint32_t* b) {
    asm volatile(
        "mma.sync.aligned.m16n8k8.row.col.f32.tf32.tf32.f32 "
        "{%0,%1,%2,%3}, {%4,%5,%6,%7}, {%8,%9}, {%0,%1,%2,%3};"
        : "+f"(c[0]), "+f"(c[1]), "+f"(c[2]), "+f"(c[3])
        : "r"(a[0]), "r"(a[1]), "r"(a[2]), "r"(a[3]),
          "r"(b[0]), "r"(b[1]));
}

// ---------------------------------------------------------------------------
// Unified tf32 tensor-core GEMM: register-staged prefetch, single smem buffer
// (27 KB), 3 CTAs/SM via launch bounds.
// MODE 0: QKV proj   MODE 1: OUT proj (+bias)
// MODE 2: AV (per bh)  MODE 3: DOTS (per bh, alpha=0.125, B n-major)
// 256 threads (8 warps 4x2), BM x BN tile, BK=32.
// ---------------------------------------------------------------------------
template<int MODE, int BM, int BN, int KTOT>
__global__ void __launch_bounds__(256, 3) mma_gemm(
    const float* __restrict__ gA, const float* __restrict__ gB,
    const float* __restrict__ bias, float* __restrict__ gC)
{
    constexpr int MI = BM / 64;
    constexpr int NI = BN / 16;
    constexpr int LDB_S = BN + 4;
    constexpr int BSZ = (MODE == 3) ? BN * 36 : 32 * LDB_S;
    constexpr int NLDA = BM / 32;
    constexpr int NLDB = BN / 32;

    __shared__ uint32_t sA[BM * 36];
    __shared__ uint32_t sB[BSZ];

    const int tid  = threadIdx.x;
    const int row0 = blockIdx.y * BM;
    const int col0 = blockIdx.x * BN;

    const float* A;
    const float* B;
    float* C;
    size_t lda, ldb, ldc;
    float alpha = 1.0f;

    if (MODE == 0) {
        A = gA; lda = DMODEL; B = gB; ldb = QKV_N; C = gC; ldc = QKV_N;
    } else if (MODE == 1) {
        A = gA; lda = DMODEL; B = gB; ldb = DMODEL; C = gC; ldc = DMODEL;
    } else if (MODE == 2) {
        const int bh = blockIdx.z, b = bh >> 4, h = bh & 15;
        A = gA + (size_t)bh * SEQ * SEQ;                               lda = SEQ;
        B = gB + (size_t)b * SEQ * QKV_N + 2 * INNER + (size_t)h * DH; ldb = QKV_N;
        C = gC + (size_t)b * SEQ * INNER + (size_t)h * DH;             ldc = INNER;
    } else {
        const int bh = blockIdx.z, b = bh >> 4, h = bh & 15;
        A = gA + (size_t)b * SEQ * QKV_N + (size_t)h * DH;             lda = QKV_N;
        B = gB + (size_t)b * SEQ * QKV_N + INNER + (size_t)h * DH;     ldb = QKV_N;
        C = gC + (size_t)bh * SEQ * SEQ;                               ldc = SEQ;
        alpha = 0.125f;
    }

    const int warp = tid >> 5, lane = tid & 31;
    const int wm = warp >> 1, wn = warp & 1;
    const int g = lane >> 2, t4 = lane & 3;

    const int aR  = tid >> 3;
    const int aC4 = tid & 7;
    const int bRk = tid / (BN / 4);
    const int bCk = tid % (BN / 4);

    float4 ra[NLDA], rb[NLDB];

    auto loadA = [&](int k0) {
        #pragma unroll
        for (int t = 0; t < NLDA; t++) {
            int r = aR + t * 32;
            ra[t] = *reinterpret_cast<const float4*>(
                &A[(size_t)(row0 + r) * lda + k0 + aC4 * 4]);
        }
    };
    auto stsA = [&]() {
        #pragma unroll
        for (int t = 0; t < NLDA; t++) {
            int r = aR + t * 32;
            uint4 u;
            u.x = f2tf32(ra[t].x); u.y = f2tf32(ra[t].y);
            u.z = f2tf32(ra[t].z); u.w = f2tf32(ra[t].w);
            *reinterpret_cast<uint4*>(&sA[r * 36 + aC4 * 4]) = u;
        }
    };
    auto loadB = [&](int k0) {
        if (MODE == 3) {
            #pragma unroll
            for (int t = 0; t < NLDB; t++) {
                int r = aR + t * 32;
                rb[t] = *reinterpret_cast<const float4*>(
                    &B[(size_t)(col0 + r) * ldb + k0 + aC4 * 4]);
            }
        } else {
            #pragma unroll
            for (int t = 0; t < NLDB; t++) {
                int r = bRk + t * (1024 / BN);
                rb[t] = *reinterpret_cast<const float4*>(
                    &B[(size_t)(k0 + r) * ldb + col0 + bCk * 4]);
            }
        }
    };
    auto stsB = [&]() {
        if (MODE == 3) {
            #pragma unroll
            for (int t = 0; t < NLDB; t++) {
                int r = aR + t * 32;
                uint4 u;
                u.x = f2tf32(rb[t].x); u.y = f2tf32(rb[t].y);
                u.z = f2tf32(rb[t].z); u.w = f2tf32(rb[t].w);
                *reinterpret_cast<uint4*>(&sB[r * 36 + aC4 * 4]) = u;
            }
        } else {
            #pragma unroll
            for (int t = 0; t < NLDB; t++) {
                int r = bRk + t * (1024 / BN);
                uint4 u;
                u.x = f2tf32(rb[t].x); u.y = f2tf32(rb[t].y);
                u.z = f2tf32(rb[t].z); u.w = f2tf32(rb[t].w);
                *reinterpret_cast<uint4*>(&sB[r * LDB_S + bCk * 4]) = u;
            }
        }
    };

    float acc[MI][NI][4] = {};

    loadA(0); loadB(0);
    stsA(); stsB();
    __syncthreads();

    for (int k0 = 0; k0 < KTOT; k0 += 32) {
        const bool more = (k0 + 32 < KTOT);
        if (more) { loadA(k0 + 32); loadB(k0 + 32); }   // LDG overlaps MMA

        #pragma unroll
        for (int kk = 0; kk < 4; kk++) {
            const int k = kk * 8;
            uint32_t af[MI][4];
            #pragma unroll
            for (int mi = 0; mi < MI; mi++) {
                int r = wm * (BM / 4) + mi * 16 + g;
                af[mi][0] = sA[r * 36 + k + t4];
                af[mi][1] = sA[(r + 8) * 36 + k + t4];
                af[mi][2] = sA[r * 36 + k + 4 + t4];
                af[mi][3] = sA[(r + 8) * 36 + k + 4 + t4];
            }
            uint32_t bf[NI][2];
            #pragma unroll
            for (int ni = 0; ni < NI; ni++) {
                int c = wn * (BN / 2) + ni * 8 + g;
                if (MODE == 3) {
                    bf[ni][0] = sB[c * 36 + k + t4];
                    bf[ni][1] = sB[c * 36 + k + 4 + t4];
                } else {
                    bf[ni][0] = sB[(k + t4) * LDB_S + c];
                    bf[ni][1] = sB[(k + 4 + t4) * LDB_S + c];
                }
            }
            #pragma unroll
            for (int mi = 0; mi < MI; mi++)
                #pragma unroll
                for (int ni = 0; ni < NI; ni++)
                    mma8(acc[mi][ni], af[mi], bf[ni]);
        }

        if (more) {
            __syncthreads();
            stsA(); stsB();
            __syncthreads();
        }
    }

    #pragma unroll
    for (int mi = 0; mi < MI; mi++) {
        int r = row0 + wm * (BM / 4) + mi * 16 + g;
        #pragma unroll
        for (int ni = 0; ni < NI; ni++) {
            int c = col0 + wn * (BN / 2) + ni * 8 + 2 * t4;
            float b0 = 0.f, b1 = 0.f;
            if (MODE == 1) { b0 = bias[c]; b1 = bias[c + 1]; }
            float2 v0, v1;
            v0.x = acc[mi][ni][0] * alpha + b0;
            v0.y = acc[mi][ni][1] * alpha + b1;
            v1.x = acc[mi][ni][2] * alpha + b0;
            v1.y = acc[mi][ni][3] * alpha + b1;
            *reinterpret_cast<float2*>(&C[(size_t)r * ldc + c]) = v0;
            *reinterpret_cast<float2*>(&C[(size_t)(r + 8) * ldc + c]) = v1;
        }
    }
}

// ---------------------------------------------------------------------------
// Fused softmax + head-mix + LayerNorm, 512 threads: one warp per head for
// softmax; one j per thread for the mix/LN pass. In-place on g_dots.
// ---------------------------------------------------------------------------
__global__ void __launch_bounds__(512, 3) softmax_mix_ln_kernel(
    float* __restrict__ dots, const float* __restrict__ W,
    const float* __restrict__ gamma, const float* __restrict__ beta)
{
    const int bi = blockIdx.x;
    const int b  = bi >> 9;
    const int i  = bi & 511;

    __shared__ float sc[HEADS][SEQ];       // 32 KB
    __shared__ float wmat[HEADS][HEADS];
    __shared__ float sg[HEADS], sb[HEADS];

    const int tid = threadIdx.x;
    if (tid < 256) wmat[tid >> 4][tid & 15] = W[tid];
    if (tid < HEADS) { sg[tid] = gamma[tid]; sb[tid] = beta[tid]; }

    // Load all 16 head rows (2048 float4s, 4 per thread)
    #pragma unroll
    for (int t = 0; t < 4; t++) {
        int idx = tid + t * 512;
        int h   = idx >> 7;
        int j4  = idx & 127;
        float4 v = *reinterpret_cast<const float4*>(
            &dots[((size_t)(b * HEADS + h) * SEQ + i) * SEQ + j4 * 4]);
        *reinterpret_cast<float4*>(&sc[h][j4 * 4]) = v;
    }
    __syncthreads();

    // Softmax: warp w handles head w (16 warps = 16 heads)
    const int h = tid >> 5, lane = tid & 31;
    {
        float v0 = sc[h][lane];
        float v1 = sc[h][lane + 32];  float v2 = sc[h][lane + 64];
        float v3 = sc[h][lane + 96];  float v4 = sc[h][lane + 128];
        // strided max over 512 with 32 lanes: 16 values each
        float mx = -1e30f;
        #pragma unroll
        for (int t = 0; t < 16; t++) mx = fmaxf(mx, sc[h][lane + t * 32]);
        #pragma unroll
        for (int o = 16; o > 0; o >>= 1)
            mx = fmaxf(mx, __shfl_xor_sync(0xffffffffu, mx, o));
        float s = 0.f;
        #pragma unroll
        for (int t = 0; t < 16; t++) {
            float e = __expf(sc[h][lane + t * 32] - mx);
            sc[h][lane + t * 32] = e;
            s += e;
        }
        #pragma unroll
        for (int o = 16; o > 0; o >>= 1)
            s += __shfl_xor_sync(0xffffffffu, s, o);
        float inv = 1.f / s;
        #pragma unroll
        for (int t = 0; t < 16; t++) sc[h][lane + t * 32] *= inv;
        (void)v0; (void)v1; (void)v2; (void)v3; (void)v4;
    }
    __syncthreads();

    // Mix + LayerNorm: exactly one j per thread
    {
        const int j = tid;
        float a[HEADS];
        #pragma unroll
        for (int hh = 0; hh < HEADS; hh++) a[hh] = sc[hh][j];
        float mixed[HEADS];
        #pragma unroll
        for (int gg = 0; gg < HEADS; gg++) {
            float s = 0.f;
            #pragma unroll
            for (int hh = 0; hh < HEADS; hh++) s = fmaf(a[hh], wmat[hh][gg], s);
            mixed[gg] = s;
        }
        float mean = 0.f;
        #pragma unroll
        for (int gg = 0; gg < HEADS; gg++) mean += mixed[gg];
        mean *= (1.f / HEADS);
        float var = 0.f;
        #pragma unroll
        for (int gg = 0; gg < HEADS; gg++) {
            float d = mixed[gg] - mean;
            var = fmaf(d, d, var);
        }
        var *= (1.f / HEADS);
        float inv = rsqrtf(var + 1e-3f);
        #pragma unroll
        for (int gg = 0; gg < HEADS; gg++) {
            float y = (mixed[gg] - mean) * inv * sg[gg] + sb[gg];
            dots[((size_t)(b * HEADS + gg) * SEQ + i) * SEQ + j] = y;
        }
    }
}

// ---------------------------------------------------------------------------
extern "C" void kernel_launch(void* const* d_in, const int* in_sizes, int n_in,
                              void* d_out, int out_size)
{
    const float* x        = (const float*)d_in[0];
    const float* w_qkv    = (const float*)d_in[1];
    const float* reattn_w = (const float*)d_in[2];
    const float* ln_gamma = (const float*)d_in[3];
    const float* ln_beta  = (const float*)d_in[4];
    const float* w_out    = (const float*)d_in[5];
    const float* b_out    = (const float*)d_in[6];
    float* out = (float*)d_out;

    float *qkv = nullptr, *dots = nullptr, *av = nullptr;
    cudaGetSymbolAddress((void**)&qkv,  g_qkv);
    cudaGetSymbolAddress((void**)&dots, g_dots);
    cudaGetSymbolAddress((void**)&av,   g_av);

    dim3 blk(256);

    // 1) QKV projection
    mma_gemm<0, 128, 128, 1024><<<dim3(QKV_N / 128, NTOK / 128), blk>>>(
        x, w_qkv, nullptr, qkv);

    // 2) dots = 0.125 * Q K^T per (b,h)
    mma_gemm<3, 128, 128, 64><<<dim3(SEQ / 128, SEQ / 128, BATCH * HEADS), blk>>>(
        qkv, qkv, nullptr, dots);

    // 3) fused softmax + head mix + LayerNorm (in place)
    softmax_mix_ln_kernel<<<BATCH * SEQ, 512>>>(dots, reattn_w, ln_gamma, ln_beta);

    // 4) AV
    mma_gemm<2, 128, 64, 512><<<dim3(1, SEQ / 128, BATCH * HEADS), blk>>>(
        dots, qkv, nullptr, av);

    // 5) output projection + bias
    mma_gemm<1, 128, 128, 1024><<<dim3(DMODEL / 128, NTOK / 128), blk>>>(
        av, w_out, b_out, out);
}

// round 6
// speedup vs baseline: 2.3882x; 2.3882x over previous
#include <cuda_runtime.h>
#include <cuda_fp16.h>
#include <stdint.h>
#include <math.h>

#define HEADS 16
#define DH    64
#define BATCH 8
#define SEQ   512
#define DMODEL 1024
#define INNER 1024            // HEADS*DH
#define QKV_N 3072            // 3*INNER
#define NTOK  4096            // BATCH*SEQ

// Scratch (device globals: allocation-free, graph-capture safe)
__device__ float  g_qkv[(size_t)NTOK * QKV_N];               // 48 MB
__device__ float  g_dots[(size_t)BATCH * HEADS * SEQ * SEQ]; // 128 MB
__device__ float  g_av[(size_t)NTOK * INNER];                // 16 MB
__device__ __half g_wqkvT[(size_t)QKV_N * DMODEL];           // 6 MB [n][k]
__device__ __half g_woutT[(size_t)DMODEL * INNER];           // 2 MB [n][k]
__device__ __half g_vT[(size_t)BATCH * HEADS * DH * SEQ];    // 8 MB [b][h][d][j]

// ---------------------------------------------------------------------------
__device__ __forceinline__ void mma16(float* c, const uint32_t* a, const uint32_t* b) {
    asm volatile(
        "mma.sync.aligned.m16n8k16.row.col.f32.f16.f16.f32 "
        "{%0,%1,%2,%3}, {%4,%5,%6,%7}, {%8,%9}, {%0,%1,%2,%3};"
        : "+f"(c[0]), "+f"(c[1]), "+f"(c[2]), "+f"(c[3])
        : "r"(a[0]), "r"(a[1]), "r"(a[2]), "r"(a[3]),
          "r"(b[0]), "r"(b[1]));
}

// ---------------------------------------------------------------------------
// Prep: transpose + fp16 convert a [K][N] fp32 matrix to [N][K] fp16.
// ---------------------------------------------------------------------------
__global__ void __launch_bounds__(256) transpose_cvt(
    const float* __restrict__ in, __half* __restrict__ out, int K, int N)
{
    __shared__ float tile[32][33];
    const int k0 = blockIdx.y * 32, n0 = blockIdx.x * 32;
    const int tx = threadIdx.x & 31, ty = threadIdx.x >> 5;
    #pragma unroll
    for (int t = 0; t < 4; t++)
        tile[ty + t * 8][tx] = in[(size_t)(k0 + ty + t * 8) * N + n0 + tx];
    __syncthreads();
    #pragma unroll
    for (int t = 0; t < 4; t++)
        out[(size_t)(n0 + ty + t * 8) * K + k0 + tx] =
            __float2half_rn(tile[tx][ty + t * 8]);
}

// Prep: vT[b][h][d][j] = (half) qkv[b][j][2*INNER + h*64 + d]
__global__ void __launch_bounds__(256) v_transpose(
    const float* __restrict__ qkv, __half* __restrict__ vT)
{
    __shared__ float tile[32][33];
    const int bh = blockIdx.z, b = bh >> 4, h = bh & 15;
    const int j0 = blockIdx.x * 32, d0 = blockIdx.y * 32;
    const int tx = threadIdx.x & 31, ty = threadIdx.x >> 5;
    const float* src = qkv + (size_t)b * SEQ * QKV_N + 2 * INNER + h * DH;
    #pragma unroll
    for (int t = 0; t < 4; t++)
        tile[ty + t * 8][tx] = src[(size_t)(j0 + ty + t * 8) * QKV_N + d0 + tx];
    __syncthreads();
    __half* dst = vT + (size_t)bh * DH * SEQ;
    #pragma unroll
    for (int t = 0; t < 4; t++)
        dst[(size_t)(d0 + ty + t * 8) * SEQ + j0 + tx] =
            __float2half_rn(tile[tx][ty + t * 8]);
}

// ---------------------------------------------------------------------------
// fp16 tensor-core GEMM (fp32 accum), register-staged prefetch, single smem
// buffer, conflict-free fragment layout (k-contiguous rows, pad 40 halves).
// MODE 0: QKV  C[4096,3072] = x f32 @ wqkvT h16[n][k]
// MODE 1: OUT  C[4096,1024] = av f32 @ woutT h16[n][k] + bias
// MODE 2: AV   per bh: C[512,64] = attn f32 @ vT h16[d][j]
// MODE 3: DOTS per bh: C[512,512] = 0.125 * Q f32 @ K f32 (B staged f32->h16)
// 256 threads (8 warps 4x2), BM x BN, BK=32 (2 x k16 steps).
// ---------------------------------------------------------------------------
template<int MODE, int BM, int BN, int KTOT>
__global__ void __launch_bounds__(256) hgemm(
    const float* __restrict__ gA, const void* __restrict__ gB,
    const float* __restrict__ bias, float* __restrict__ gC)
{
    constexpr bool BHALF = (MODE != 3);
    constexpr int MI = BM / 64;
    constexpr int NI = BN / 16;
    constexpr int LK = 40;               // padded k-stride in halves
    constexpr int NLDA   = BM / 32;      // float4 A loads per thread
    constexpr int NLDB_F = BN / 32;      // float4 B loads (MODE3)
    constexpr int NLDB_H = (BN + 63) / 64; // uint4 half B loads

    __shared__ __align__(16) __half sA[BM * LK];
    __shared__ __align__(16) __half sB[BN * LK];

    const int tid  = threadIdx.x;
    const int row0 = blockIdx.y * BM;
    const int col0 = blockIdx.x * BN;

    const float*  A  = nullptr;
    const __half* Bh = nullptr;
    const float*  Bf = nullptr;
    float* C;
    size_t lda, ldb, ldc;
    float alpha = 1.0f;

    if (MODE == 0) {
        A = gA; lda = DMODEL;
        Bh = (const __half*)gB; ldb = DMODEL;
        C = gC; ldc = QKV_N;
    } else if (MODE == 1) {
        A = gA; lda = DMODEL;
        Bh = (const __half*)gB; ldb = DMODEL;
        C = gC; ldc = DMODEL;
    } else if (MODE == 2) {
        const int bh = blockIdx.z, b = bh >> 4, h = bh & 15;
        A = gA + (size_t)bh * SEQ * SEQ; lda = SEQ;
        Bh = (const __half*)gB + (size_t)bh * DH * SEQ; ldb = SEQ;
        C = gC + (size_t)b * SEQ * INNER + (size_t)h * DH; ldc = INNER;
    } else {
        const int bh = blockIdx.z, b = bh >> 4, h = bh & 15;
        A = gA + (size_t)b * SEQ * QKV_N + (size_t)h * DH; lda = QKV_N;
        Bf = (const float*)gB + (size_t)b * SEQ * QKV_N + INNER + (size_t)h * DH;
        ldb = QKV_N;
        C = gC + (size_t)bh * SEQ * SEQ; ldc = SEQ;
        alpha = 0.125f;
    }

    const int warp = tid >> 5, lane = tid & 31;
    const int wm = warp >> 1, wn = warp & 1;
    const int g = lane >> 2, t4 = lane & 3;

    const int aR  = tid >> 3;            // 0..31 (fp32 staging row base)
    const int aC4 = tid & 7;             // float4 col
    const int hR  = tid >> 2;            // 0..63 (half staging row base)
    const int hC  = tid & 3;             // uint4 col (8 halves each)

    float4 ra[NLDA];
    float4 rbf[NLDB_F];
    uint4  rbh[NLDB_H];

    auto loadA = [&](int k0) {
        #pragma unroll
        for (int t = 0; t < NLDA; t++) {
            int r = aR + t * 32;
            ra[t] = *reinterpret_cast<const float4*>(
                &A[(size_t)(row0 + r) * lda + k0 + aC4 * 4]);
        }
    };
    auto stsA = [&]() {
        #pragma unroll
        for (int t = 0; t < NLDA; t++) {
            int r = aR + t * 32;
            __half2 h01 = __floats2half2_rn(ra[t].x, ra[t].y);
            __half2 h23 = __floats2half2_rn(ra[t].z, ra[t].w);
            uint2 u;
            u.x = *reinterpret_cast<uint32_t*>(&h01);
            u.y = *reinterpret_cast<uint32_t*>(&h23);
            *reinterpret_cast<uint2*>(&sA[(size_t)r * LK + aC4 * 4]) = u;
        }
    };
    auto loadB = [&](int k0) {
        if (BHALF) {
            #pragma unroll
            for (int p = 0; p < NLDB_H; p++) {
                int r = hR + p * 64;
                rbh[p] = *reinterpret_cast<const uint4*>(
                    &Bh[(size_t)(col0 + r) * ldb + k0 + hC * 8]);
            }
        } else {
            #pragma unroll
            for (int t = 0; t < NLDB_F; t++) {
                int r = aR + t * 32;
                rbf[t] = *reinterpret_cast<const float4*>(
                    &Bf[(size_t)(col0 + r) * ldb + k0 + aC4 * 4]);
            }
        }
    };
    auto stsB = [&]() {
        if (BHALF) {
            #pragma unroll
            for (int p = 0; p < NLDB_H; p++) {
                int r = hR + p * 64;
                *reinterpret_cast<uint4*>(&sB[(size_t)r * LK + hC * 8]) = rbh[p];
            }
        } else {
            #pragma unroll
            for (int t = 0; t < NLDB_F; t++) {
                int r = aR + t * 32;
                __half2 h01 = __floats2half2_rn(rbf[t].x, rbf[t].y);
                __half2 h23 = __floats2half2_rn(rbf[t].z, rbf[t].w);
                uint2 u;
                u.x = *reinterpret_cast<uint32_t*>(&h01);
                u.y = *reinterpret_cast<uint32_t*>(&h23);
                *reinterpret_cast<uint2*>(&sB[(size_t)r * LK + aC4 * 4]) = u;
            }
        }
    };

    float acc[MI][NI][4] = {};

    loadA(0); loadB(0);
    stsA(); stsB();
    __syncthreads();

    for (int k0 = 0; k0 < KTOT; k0 += 32) {
        const bool more = (k0 + 32 < KTOT);
        if (more) { loadA(k0 + 32); loadB(k0 + 32); }   // LDG overlaps MMA

        #pragma unroll
        for (int kk = 0; kk < 2; kk++) {
            const int ka = kk * 16 + 2 * t4;
            uint32_t af[MI][4];
            #pragma unroll
            for (int mi = 0; mi < MI; mi++) {
                int r = wm * (BM / 4) + mi * 16 + g;
                af[mi][0] = *reinterpret_cast<const uint32_t*>(&sA[r * LK + ka]);
                af[mi][1] = *reinterpret_cast<const uint32_t*>(&sA[(r + 8) * LK + ka]);
                af[mi][2] = *reinterpret_cast<const uint32_t*>(&sA[r * LK + ka + 8]);
                af[mi][3] = *reinterpret_cast<const uint32_t*>(&sA[(r + 8) * LK + ka + 8]);
            }
            uint32_t bf[NI][2];
            #pragma unroll
            for (int ni = 0; ni < NI; ni++) {
                int c = wn * (BN / 2) + ni * 8 + g;
                bf[ni][0] = *reinterpret_cast<const uint32_t*>(&sB[c * LK + ka]);
                bf[ni][1] = *reinterpret_cast<const uint32_t*>(&sB[c * LK + ka + 8]);
            }
            #pragma unroll
            for (int mi = 0; mi < MI; mi++)
                #pragma unroll
                for (int ni = 0; ni < NI; ni++)
                    mma16(acc[mi][ni], af[mi], bf[ni]);
        }

        if (more) {
            __syncthreads();
            stsA(); stsB();
            __syncthreads();
        }
    }

    // Epilogue (accumulator layout identical to tf32 path)
    #pragma unroll
    for (int mi = 0; mi < MI; mi++) {
        int r = row0 + wm * (BM / 4) + mi * 16 + g;
        #pragma unroll
        for (int ni = 0; ni < NI; ni++) {
            int c = col0 + wn * (BN / 2) + ni * 8 + 2 * t4;
            float b0 = 0.f, b1 = 0.f;
            if (MODE == 1) { b0 = bias[c]; b1 = bias[c + 1]; }
            float2 v0, v1;
            v0.x = acc[mi][ni][0] * alpha + b0;
            v0.y = acc[mi][ni][1] * alpha + b1;
            v1.x = acc[mi][ni][2] * alpha + b0;
            v1.y = acc[mi][ni][3] * alpha + b1;
            *reinterpret_cast<float2*>(&C[(size_t)r * ldc + c]) = v0;
            *reinterpret_cast<float2*>(&C[(size_t)(r + 8) * ldc + c]) = v1;
        }
    }
}

// ---------------------------------------------------------------------------
// Fused softmax + head-mix + LayerNorm (R3 version: 256 threads, in-place).
// ---------------------------------------------------------------------------
__global__ void __launch_bounds__(256) softmax_mix_ln_kernel(
    float* __restrict__ dots, const float* __restrict__ W,
    const float* __restrict__ gamma, const float* __restrict__ beta)
{
    const int bi = blockIdx.x;
    const int b  = bi >> 9;
    const int i  = bi & 511;

    __shared__ float sc[HEADS][SEQ];
    __shared__ float wmat[HEADS][HEADS];
    __shared__ float sg[HEADS], sb[HEADS];

    const int tid = threadIdx.x;
    wmat[tid >> 4][tid & 15] = W[tid];
    if (tid < HEADS) { sg[tid] = gamma[tid]; sb[tid] = beta[tid]; }

    #pragma unroll
    for (int t = 0; t < 8; t++) {
        int idx = tid + t * 256;
        int h   = idx >> 7;
        int j4  = idx & 127;
        float4 v = *reinterpret_cast<const float4*>(
            &dots[((size_t)(b * HEADS + h) * SEQ + i) * SEQ + j4 * 4]);
        *reinterpret_cast<float4*>(&sc[h][j4 * 4]) = v;
    }
    __syncthreads();

    const int warp = tid >> 5, lane = tid & 31;
    #pragma unroll
    for (int hh = 0; hh < 2; hh++) {
        int h = warp * 2 + hh;
        float mx = -1e30f;
        for (int j = lane; j < SEQ; j += 32) mx = fmaxf(mx, sc[h][j]);
        #pragma unroll
        for (int o = 16; o > 0; o >>= 1)
            mx = fmaxf(mx, __shfl_xor_sync(0xffffffffu, mx, o));
        float s = 0.f;
        for (int j = lane; j < SEQ; j += 32) {
            float e = __expf(sc[h][j] - mx);
            sc[h][j] = e;
            s += e;
        }
        #pragma unroll
        for (int o = 16; o > 0; o >>= 1)
            s += __shfl_xor_sync(0xffffffffu, s, o);
        float inv = 1.f / s;
        for (int j = lane; j < SEQ; j += 32) sc[h][j] *= inv;
    }
    __syncthreads();

    for (int j = tid; j < SEQ; j += 256) {
        float a[HEADS];
        #pragma unroll
        for (int h = 0; h < HEADS; h++) a[h] = sc[h][j];
        float mixed[HEADS];
        #pragma unroll
        for (int gg = 0; gg < HEADS; gg++) {
            float s = 0.f;
            #pragma unroll
            for (int h = 0; h < HEADS; h++) s = fmaf(a[h], wmat[h][gg], s);
            mixed[gg] = s;
        }
        float mean = 0.f;
        #pragma unroll
        for (int gg = 0; gg < HEADS; gg++) mean += mixed[gg];
        mean *= (1.f / HEADS);
        float var = 0.f;
        #pragma unroll
        for (int gg = 0; gg < HEADS; gg++) {
            float d = mixed[gg] - mean;
            var = fmaf(d, d, var);
        }
        var *= (1.f / HEADS);
        float inv = rsqrtf(var + 1e-3f);
        #pragma unroll
        for (int gg = 0; gg < HEADS; gg++) {
            float y = (mixed[gg] - mean) * inv * sg[gg] + sb[gg];
            dots[((size_t)(b * HEADS + gg) * SEQ + i) * SEQ + j] = y;
        }
    }
}

// ---------------------------------------------------------------------------
extern "C" void kernel_launch(void* const* d_in, const int* in_sizes, int n_in,
                              void* d_out, int out_size)
{
    const float* x        = (const float*)d_in[0];
    const float* w_qkv    = (const float*)d_in[1];
    const float* reattn_w = (const float*)d_in[2];
    const float* ln_gamma = (const float*)d_in[3];
    const float* ln_beta  = (const float*)d_in[4];
    const float* w_out    = (const float*)d_in[5];
    const float* b_out    = (const float*)d_in[6];
    float* out = (float*)d_out;

    float *qkv = nullptr, *dots = nullptr, *av = nullptr;
    __half *wqkvT = nullptr, *woutT = nullptr, *vT = nullptr;
    cudaGetSymbolAddress((void**)&qkv,   g_qkv);
    cudaGetSymbolAddress((void**)&dots,  g_dots);
    cudaGetSymbolAddress((void**)&av,    g_av);
    cudaGetSymbolAddress((void**)&wqkvT, g_wqkvT);
    cudaGetSymbolAddress((void**)&woutT, g_woutT);
    cudaGetSymbolAddress((void**)&vT,    g_vT);

    dim3 blk(256);

    // 0) weight prep: transpose + fp16 convert
    transpose_cvt<<<dim3(QKV_N / 32, DMODEL / 32), blk>>>(w_qkv, wqkvT, DMODEL, QKV_N);
    transpose_cvt<<<dim3(DMODEL / 32, DMODEL / 32), blk>>>(w_out, woutT, DMODEL, DMODEL);

    // 1) QKV projection
    hgemm<0, 128, 128, 1024><<<dim3(QKV_N / 128, NTOK / 128), blk>>>(
        x, wqkvT, nullptr, qkv);

    // 1b) V transpose to [b][h][d][j] fp16
    v_transpose<<<dim3(SEQ / 32, DH / 32, BATCH * HEADS), blk>>>(qkv, vT);

    // 2) dots = 0.125 * Q K^T per (b,h)
    hgemm<3, 128, 128, 64><<<dim3(SEQ / 128, SEQ / 128, BATCH * HEADS), blk>>>(
        qkv, qkv, nullptr, dots);

    // 3) fused softmax + head mix + LayerNorm (in place)
    softmax_mix_ln_kernel<<<BATCH * SEQ, blk>>>(dots, reattn_w, ln_gamma, ln_beta);

    // 4) AV
    hgemm<2, 128, 64, 512><<<dim3(1, SEQ / 128, BATCH * HEADS), blk>>>(
        dots, vT, nullptr, av);

    // 5) output projection + bias
    hgemm<1, 128, 128, 1024><<<dim3(DMODEL / 128, NTOK / 128), blk>>>(
        av, woutT, b_out, out);
}

// round 7
// speedup vs baseline: 2.5083x; 1.0503x over previous
#include <cuda_runtime.h>
#include <cuda_fp16.h>
#include <stdint.h>
#include <math.h>

#define HEADS 16
#define DH    64
#define BATCH 8
#define SEQ   512
#define DMODEL 1024
#define INNER 1024            // HEADS*DH
#define QKV_N 3072            // 3*INNER
#define NTOK  4096            // BATCH*SEQ

// Scratch (device globals: allocation-free, graph-capture safe)
__device__ __half g_qkvh[(size_t)NTOK * QKV_N];              // 24 MB [tok][3*inner]
__device__ float  g_dots[(size_t)BATCH * HEADS * SEQ * SEQ]; // 128 MB fp32 logits
__device__ __half g_attnh[(size_t)BATCH * HEADS * SEQ * SEQ];// 64 MB post-LN attn
__device__ __half g_avh[(size_t)NTOK * INNER];               // 8 MB
__device__ __half g_wqkvT[(size_t)QKV_N * DMODEL];           // 6 MB [n][k]
__device__ __half g_woutT[(size_t)DMODEL * INNER];           // 2 MB [n][k]
__device__ __half g_vT[(size_t)BATCH * HEADS * DH * SEQ];    // 8 MB [b][h][d][j]

// ---------------------------------------------------------------------------
__device__ __forceinline__ void mma16(float* c, const uint32_t* a, const uint32_t* b) {
    asm volatile(
        "mma.sync.aligned.m16n8k16.row.col.f32.f16.f16.f32 "
        "{%0,%1,%2,%3}, {%4,%5,%6,%7}, {%8,%9}, {%0,%1,%2,%3};"
        : "+f"(c[0]), "+f"(c[1]), "+f"(c[2]), "+f"(c[3])
        : "r"(a[0]), "r"(a[1]), "r"(a[2]), "r"(a[3]),
          "r"(b[0]), "r"(b[1]));
}

// ---------------------------------------------------------------------------
// Prep: transpose + fp16 convert a [K][N] fp32 matrix to [N][K] fp16.
// ---------------------------------------------------------------------------
__global__ void __launch_bounds__(256) transpose_cvt(
    const float* __restrict__ in, __half* __restrict__ out, int K, int N)
{
    __shared__ float tile[32][33];
    const int k0 = blockIdx.y * 32, n0 = blockIdx.x * 32;
    const int tx = threadIdx.x & 31, ty = threadIdx.x >> 5;
    #pragma unroll
    for (int t = 0; t < 4; t++)
        tile[ty + t * 8][tx] = in[(size_t)(k0 + ty + t * 8) * N + n0 + tx];
    __syncthreads();
    #pragma unroll
    for (int t = 0; t < 4; t++)
        out[(size_t)(n0 + ty + t * 8) * K + k0 + tx] =
            __float2half_rn(tile[tx][ty + t * 8]);
}

// Prep: vT[b][h][d][j] = qkvh[b][j][2*INNER + h*64 + d]   (half -> half)
__global__ void __launch_bounds__(256) v_transpose(
    const __half* __restrict__ qkvh, __half* __restrict__ vT)
{
    __shared__ __half tile[32][34];
    const int bh = blockIdx.z, b = bh >> 4, h = bh & 15;
    const int j0 = blockIdx.x * 32, d0 = blockIdx.y * 32;
    const int tx = threadIdx.x & 31, ty = threadIdx.x >> 5;
    const __half* src = qkvh + (size_t)b * SEQ * QKV_N + 2 * INNER + h * DH;
    #pragma unroll
    for (int t = 0; t < 4; t++)
        tile[ty + t * 8][tx] = src[(size_t)(j0 + ty + t * 8) * QKV_N + d0 + tx];
    __syncthreads();
    __half* dst = vT + (size_t)bh * DH * SEQ;
    #pragma unroll
    for (int t = 0; t < 4; t++)
        dst[(size_t)(d0 + ty + t * 8) * SEQ + j0 + tx] = tile[tx][ty + t * 8];
}

// ---------------------------------------------------------------------------
// fp16 tensor-core GEMM (fp32 accum), register-staged prefetch, single smem
// buffer, conflict-free fragment layout (k-contiguous rows, pad LK=40 halves).
// MODE 0: QKV  qkvh[4096,3072](h) = x(f32) @ wqkvT(h)[n][k]
// MODE 1: OUT  out[4096,1024](f32) = avh(h) @ woutT(h) + bias
// MODE 2: AV   per bh: avh[512,64](h) = attnh(h) @ vT(h)[d][j]
// MODE 3: DOTS per bh: dots[512,512](f32) = 0.125 * Qh @ Kh^T
// 256 threads (8 warps 4x2), BM x BN, BK=32 (2 x k16 steps).
// ---------------------------------------------------------------------------
template<int MODE, int BM, int BN, int KTOT>
__global__ void __launch_bounds__(256) hgemm(
    const void* __restrict__ gA, const void* __restrict__ gB,
    const float* __restrict__ bias, void* __restrict__ gC)
{
    constexpr bool AHALF = (MODE != 0);
    constexpr bool CHALF = (MODE == 0 || MODE == 2);
    constexpr int MI = BM / 64;
    constexpr int NI = BN / 16;
    constexpr int LK = 40;                 // padded k-stride in halves
    constexpr int NLDA_F = BM / 32;        // float4 A loads (MODE0)
    constexpr int NLDA_H = BM / 64;        // uint4 half A loads
    constexpr int NLDB_H = BN / 64;        // uint4 half B loads

    __shared__ __align__(16) __half sA[BM * LK];
    __shared__ __align__(16) __half sB[BN * LK];

    const int tid  = threadIdx.x;
    const int row0 = blockIdx.y * BM;
    const int col0 = blockIdx.x * BN;

    const float*  Af = nullptr;
    const __half* Ah = nullptr;
    const __half* Bh = nullptr;
    float*  Cf = nullptr;
    __half* Ch = nullptr;
    size_t lda, ldb, ldc;
    float alpha = 1.0f;

    if (MODE == 0) {
        Af = (const float*)gA;  lda = DMODEL;
        Bh = (const __half*)gB; ldb = DMODEL;
        Ch = (__half*)gC;       ldc = QKV_N;
    } else if (MODE == 1) {
        Ah = (const __half*)gA; lda = DMODEL;
        Bh = (const __half*)gB; ldb = DMODEL;
        Cf = (float*)gC;        ldc = DMODEL;
    } else if (MODE == 2) {
        const int bh = blockIdx.z, b = bh >> 4, h = bh & 15;
        Ah = (const __half*)gA + (size_t)bh * SEQ * SEQ;          lda = SEQ;
        Bh = (const __half*)gB + (size_t)bh * DH * SEQ;           ldb = SEQ;
        Ch = (__half*)gC + (size_t)b * SEQ * INNER + (size_t)h * DH; ldc = INNER;
    } else {
        const int bh = blockIdx.z, b = bh >> 4, h = bh & 15;
        Ah = (const __half*)gA + (size_t)b * SEQ * QKV_N + (size_t)h * DH;
        lda = QKV_N;
        Bh = (const __half*)gB + (size_t)b * SEQ * QKV_N + INNER + (size_t)h * DH;
        ldb = QKV_N;
        Cf = (float*)gC + (size_t)bh * SEQ * SEQ;                 ldc = SEQ;
        alpha = 0.125f;
    }

    const int warp = tid >> 5, lane = tid & 31;
    const int wm = warp >> 1, wn = warp & 1;
    const int g = lane >> 2, t4 = lane & 3;

    const int aR  = tid >> 3;            // fp32 staging row base (0..31)
    const int aC4 = tid & 7;             // float4 col
    const int hR  = tid >> 2;            // half staging row base (0..63)
    const int hC  = tid & 3;             // uint4 col (8 halves each)

    float4 raf[NLDA_F];
    uint4  rah[NLDA_H];
    uint4  rbh[NLDB_H];

    auto loadA = [&](int k0) {
        if (AHALF) {
            #pragma unroll
            for (int p = 0; p < NLDA_H; p++) {
                int r = hR + p * 64;
                rah[p] = *reinterpret_cast<const uint4*>(
                    &Ah[(size_t)(row0 + r) * lda + k0 + hC * 8]);
            }
        } else {
            #pragma unroll
            for (int t = 0; t < NLDA_F; t++) {
                int r = aR + t * 32;
                raf[t] = *reinterpret_cast<const float4*>(
                    &Af[(size_t)(row0 + r) * lda + k0 + aC4 * 4]);
            }
        }
    };
    auto stsA = [&]() {
        if (AHALF) {
            #pragma unroll
            for (int p = 0; p < NLDA_H; p++) {
                int r = hR + p * 64;
                *reinterpret_cast<uint4*>(&sA[(size_t)r * LK + hC * 8]) = rah[p];
            }
        } else {
            #pragma unroll
            for (int t = 0; t < NLDA_F; t++) {
                int r = aR + t * 32;
                __half2 h01 = __floats2half2_rn(raf[t].x, raf[t].y);
                __half2 h23 = __floats2half2_rn(raf[t].z, raf[t].w);
                uint2 u;
                u.x = *reinterpret_cast<uint32_t*>(&h01);
                u.y = *reinterpret_cast<uint32_t*>(&h23);
                *reinterpret_cast<uint2*>(&sA[(size_t)r * LK + aC4 * 4]) = u;
            }
        }
    };
    auto loadB = [&](int k0) {
        #pragma unroll
        for (int p = 0; p < NLDB_H; p++) {
            int r = hR + p * 64;
            rbh[p] = *reinterpret_cast<const uint4*>(
                &Bh[(size_t)(col0 + r) * ldb + k0 + hC * 8]);
        }
    };
    auto stsB = [&]() {
        #pragma unroll
        for (int p = 0; p < NLDB_H; p++) {
            int r = hR + p * 64;
            *reinterpret_cast<uint4*>(&sB[(size_t)r * LK + hC * 8]) = rbh[p];
        }
    };

    float acc[MI][NI][4] = {};

    loadA(0); loadB(0);
    stsA(); stsB();
    __syncthreads();

    for (int k0 = 0; k0 < KTOT; k0 += 32) {
        const bool more = (k0 + 32 < KTOT);
        if (more) { loadA(k0 + 32); loadB(k0 + 32); }   // LDG overlaps MMA

        #pragma unroll
        for (int kk = 0; kk < 2; kk++) {
            const int ka = kk * 16 + 2 * t4;
            uint32_t af[MI][4];
            #pragma unroll
            for (int mi = 0; mi < MI; mi++) {
                int r = wm * (BM / 4) + mi * 16 + g;
                af[mi][0] = *reinterpret_cast<const uint32_t*>(&sA[r * LK + ka]);
                af[mi][1] = *reinterpret_cast<const uint32_t*>(&sA[(r + 8) * LK + ka]);
                af[mi][2] = *reinterpret_cast<const uint32_t*>(&sA[r * LK + ka + 8]);
                af[mi][3] = *reinterpret_cast<const uint32_t*>(&sA[(r + 8) * LK + ka + 8]);
            }
            uint32_t bf[NI][2];
            #pragma unroll
            for (int ni = 0; ni < NI; ni++) {
                int c = wn * (BN / 2) + ni * 8 + g;
                bf[ni][0] = *reinterpret_cast<const uint32_t*>(&sB[c * LK + ka]);
                bf[ni][1] = *reinterpret_cast<const uint32_t*>(&sB[c * LK + ka + 8]);
            }
            #pragma unroll
            for (int mi = 0; mi < MI; mi++)
                #pragma unroll
                for (int ni = 0; ni < NI; ni++)
                    mma16(acc[mi][ni], af[mi], bf[ni]);
        }

        if (more) {
            __syncthreads();
            stsA(); stsB();
            __syncthreads();
        }
    }

    // Epilogue
    #pragma unroll
    for (int mi = 0; mi < MI; mi++) {
        int r = row0 + wm * (BM / 4) + mi * 16 + g;
        #pragma unroll
        for (int ni = 0; ni < NI; ni++) {
            int c = col0 + wn * (BN / 2) + ni * 8 + 2 * t4;
            if (CHALF) {
                __half2 hv0 = __floats2half2_rn(acc[mi][ni][0], acc[mi][ni][1]);
                __half2 hv1 = __floats2half2_rn(acc[mi][ni][2], acc[mi][ni][3]);
                *reinterpret_cast<__half2*>(&Ch[(size_t)r * ldc + c]) = hv0;
                *reinterpret_cast<__half2*>(&Ch[(size_t)(r + 8) * ldc + c]) = hv1;
            } else {
                float b0 = 0.f, b1 = 0.f;
                if (MODE == 1) { b0 = bias[c]; b1 = bias[c + 1]; }
                float2 v0, v1;
                v0.x = acc[mi][ni][0] * alpha + b0;
                v0.y = acc[mi][ni][1] * alpha + b1;
                v1.x = acc[mi][ni][2] * alpha + b0;
                v1.y = acc[mi][ni][3] * alpha + b1;
                *reinterpret_cast<float2*>(&Cf[(size_t)r * ldc + c]) = v0;
                *reinterpret_cast<float2*>(&Cf[(size_t)(r + 8) * ldc + c]) = v1;
            }
        }
    }
}

// ---------------------------------------------------------------------------
// Fused softmax + head-mix + LayerNorm. Reads fp32 dots, writes fp16 attn.
// ---------------------------------------------------------------------------
__global__ void __launch_bounds__(256) softmax_mix_ln_kernel(
    const float* __restrict__ dots, __half* __restrict__ attnh,
    const float* __restrict__ W,
    const float* __restrict__ gamma, const float* __restrict__ beta)
{
    const int bi = blockIdx.x;
    const int b  = bi >> 9;
    const int i  = bi & 511;

    __shared__ float sc[HEADS][SEQ];
    __shared__ float wmat[HEADS][HEADS];
    __shared__ float sg[HEADS], sb[HEADS];

    const int tid = threadIdx.x;
    wmat[tid >> 4][tid & 15] = W[tid];
    if (tid < HEADS) { sg[tid] = gamma[tid]; sb[tid] = beta[tid]; }

    #pragma unroll
    for (int t = 0; t < 8; t++) {
        int idx = tid + t * 256;
        int h   = idx >> 7;
        int j4  = idx & 127;
        float4 v = *reinterpret_cast<const float4*>(
            &dots[((size_t)(b * HEADS + h) * SEQ + i) * SEQ + j4 * 4]);
        *reinterpret_cast<float4*>(&sc[h][j4 * 4]) = v;
    }
    __syncthreads();

    const int warp = tid >> 5, lane = tid & 31;
    #pragma unroll
    for (int hh = 0; hh < 2; hh++) {
        int h = warp * 2 + hh;
        float mx = -1e30f;
        for (int j = lane; j < SEQ; j += 32) mx = fmaxf(mx, sc[h][j]);
        #pragma unroll
        for (int o = 16; o > 0; o >>= 1)
            mx = fmaxf(mx, __shfl_xor_sync(0xffffffffu, mx, o));
        float s = 0.f;
        for (int j = lane; j < SEQ; j += 32) {
            float e = __expf(sc[h][j] - mx);
            sc[h][j] = e;
            s += e;
        }
        #pragma unroll
        for (int o = 16; o > 0; o >>= 1)
            s += __shfl_xor_sync(0xffffffffu, s, o);
        float inv = 1.f / s;
        for (int j = lane; j < SEQ; j += 32) sc[h][j] *= inv;
    }
    __syncthreads();

    for (int j = tid; j < SEQ; j += 256) {
        float a[HEADS];
        #pragma unroll
        for (int h = 0; h < HEADS; h++) a[h] = sc[h][j];
        float mixed[HEADS];
        #pragma unroll
        for (int gg = 0; gg < HEADS; gg++) {
            float s = 0.f;
            #pragma unroll
            for (int h = 0; h < HEADS; h++) s = fmaf(a[h], wmat[h][gg], s);
            mixed[gg] = s;
        }
        float mean = 0.f;
        #pragma unroll
        for (int gg = 0; gg < HEADS; gg++) mean += mixed[gg];
        mean *= (1.f / HEADS);
        float var = 0.f;
        #pragma unroll
        for (int gg = 0; gg < HEADS; gg++) {
            float d = mixed[gg] - mean;
            var = fmaf(d, d, var);
        }
        var *= (1.f / HEADS);
        float inv = rsqrtf(var + 1e-3f);
        #pragma unroll
        for (int gg = 0; gg < HEADS; gg++) {
            float y = (mixed[gg] - mean) * inv * sg[gg] + sb[gg];
            attnh[((size_t)(b * HEADS + gg) * SEQ + i) * SEQ + j] =
                __float2half_rn(y);
        }
    }
}

// ---------------------------------------------------------------------------
extern "C" void kernel_launch(void* const* d_in, const int* in_sizes, int n_in,
                              void* d_out, int out_size)
{
    const float* x        = (const float*)d_in[0];
    const float* w_qkv    = (const float*)d_in[1];
    const float* reattn_w = (const float*)d_in[2];
    const float* ln_gamma = (const float*)d_in[3];
    const float* ln_beta  = (const float*)d_in[4];
    const float* w_out    = (const float*)d_in[5];
    const float* b_out    = (const float*)d_in[6];
    float* out = (float*)d_out;

    __half *qkvh = nullptr, *attnh = nullptr, *avh = nullptr;
    __half *wqkvT = nullptr, *woutT = nullptr, *vT = nullptr;
    float *dots = nullptr;
    cudaGetSymbolAddress((void**)&qkvh,  g_qkvh);
    cudaGetSymbolAddress((void**)&dots,  g_dots);
    cudaGetSymbolAddress((void**)&attnh, g_attnh);
    cudaGetSymbolAddress((void**)&avh,   g_avh);
    cudaGetSymbolAddress((void**)&wqkvT, g_wqkvT);
    cudaGetSymbolAddress((void**)&woutT, g_woutT);
    cudaGetSymbolAddress((void**)&vT,    g_vT);

    dim3 blk(256);

    // 0) weight prep: transpose + fp16 convert
    transpose_cvt<<<dim3(QKV_N / 32, DMODEL / 32), blk>>>(w_qkv, wqkvT, DMODEL, QKV_N);
    transpose_cvt<<<dim3(DMODEL / 32, DMODEL / 32), blk>>>(w_out, woutT, DMODEL, DMODEL);

    // 1) QKV projection -> fp16
    hgemm<0, 128, 128, 1024><<<dim3(QKV_N / 128, NTOK / 128), blk>>>(
        x, wqkvT, nullptr, qkvh);

    // 1b) V transpose to [b][h][d][j] fp16
    v_transpose<<<dim3(SEQ / 32, DH / 32, BATCH * HEADS), blk>>>(qkvh, vT);

    // 2) dots = 0.125 * Q K^T per (b,h) -> fp32
    hgemm<3, 128, 128, 64><<<dim3(SEQ / 128, SEQ / 128, BATCH * HEADS), blk>>>(
        qkvh, qkvh, nullptr, dots);

    // 3) fused softmax + head mix + LayerNorm -> fp16 attn
    softmax_mix_ln_kernel<<<BATCH * SEQ, blk>>>(dots, attnh, reattn_w, ln_gamma, ln_beta);

    // 4) AV -> fp16
    hgemm<2, 128, 64, 512><<<dim3(1, SEQ / 128, BATCH * HEADS), blk>>>(
        attnh, vT, nullptr, avh);

    // 5) output projection + bias -> fp32 out
    hgemm<1, 128, 128, 1024><<<dim3(DMODEL / 128, NTOK / 128), blk>>>(
        avh, woutT, b_out, out);
}

// round 8
// speedup vs baseline: 3.1010x; 1.2363x over previous
#include <cuda_runtime.h>
#include <cuda_fp16.h>
#include <stdint.h>
#include <math.h>

#define HEADS 16
#define DH    64
#define BATCH 8
#define SEQ   512
#define DMODEL 1024
#define INNER 1024            // HEADS*DH
#define QKV_N 3072            // 3*INNER
#define NTOK  4096            // BATCH*SEQ

// Scratch (device globals: allocation-free, graph-capture safe)
__device__ __half g_qkvh[(size_t)NTOK * QKV_N];              // 24 MB
__device__ float  g_dots[(size_t)BATCH * HEADS * SEQ * SEQ]; // 128 MB fp32 logits
__device__ __half g_attnh[(size_t)BATCH * HEADS * SEQ * SEQ];// 64 MB post-LN attn
__device__ __half g_avh[(size_t)NTOK * INNER];               // 8 MB
__device__ __half g_wqkvT[(size_t)QKV_N * DMODEL];           // 6 MB [n][k]
__device__ __half g_woutT[(size_t)DMODEL * INNER];           // 2 MB [n][k]
__device__ __half g_vT[(size_t)BATCH * HEADS * DH * SEQ];    // 8 MB [b][h][d][j]

// ---------------------------------------------------------------------------
__device__ __forceinline__ void mma16(float* c, const uint32_t* a, const uint32_t* b) {
    asm volatile(
        "mma.sync.aligned.m16n8k16.row.col.f32.f16.f16.f32 "
        "{%0,%1,%2,%3}, {%4,%5,%6,%7}, {%8,%9}, {%0,%1,%2,%3};"
        : "+f"(c[0]), "+f"(c[1]), "+f"(c[2]), "+f"(c[3])
        : "r"(a[0]), "r"(a[1]), "r"(a[2]), "r"(a[3]),
          "r"(b[0]), "r"(b[1]));
}

__device__ __forceinline__ void ldsm_x4(uint32_t* r, const __half* p) {
    uint32_t addr = (uint32_t)__cvta_generic_to_shared(p);
    asm volatile(
        "ldmatrix.sync.aligned.m8n8.x4.shared.b16 {%0,%1,%2,%3}, [%4];"
        : "=r"(r[0]), "=r"(r[1]), "=r"(r[2]), "=r"(r[3]) : "r"(addr));
}

// ---------------------------------------------------------------------------
// Prep: transpose + fp16 convert a [K][N] fp32 matrix to [N][K] fp16.
// ---------------------------------------------------------------------------
__global__ void __launch_bounds__(256) transpose_cvt(
    const float* __restrict__ in, __half* __restrict__ out, int K, int N)
{
    __shared__ float tile[32][33];
    const int k0 = blockIdx.y * 32, n0 = blockIdx.x * 32;
    const int tx = threadIdx.x & 31, ty = threadIdx.x >> 5;
    #pragma unroll
    for (int t = 0; t < 4; t++)
        tile[ty + t * 8][tx] = in[(size_t)(k0 + ty + t * 8) * N + n0 + tx];
    __syncthreads();
    #pragma unroll
    for (int t = 0; t < 4; t++)
        out[(size_t)(n0 + ty + t * 8) * K + k0 + tx] =
            __float2half_rn(tile[tx][ty + t * 8]);
}

// Prep: vT[b][h][d][j] = qkvh[b][j][2*INNER + h*64 + d]
__global__ void __launch_bounds__(256) v_transpose(
    const __half* __restrict__ qkvh, __half* __restrict__ vT)
{
    __shared__ __half tile[32][34];
    const int bh = blockIdx.z, b = bh >> 4, h = bh & 15;
    const int j0 = blockIdx.x * 32, d0 = blockIdx.y * 32;
    const int tx = threadIdx.x & 31, ty = threadIdx.x >> 5;
    const __half* src = qkvh + (size_t)b * SEQ * QKV_N + 2 * INNER + h * DH;
    #pragma unroll
    for (int t = 0; t < 4; t++)
        tile[ty + t * 8][tx] = src[(size_t)(j0 + ty + t * 8) * QKV_N + d0 + tx];
    __syncthreads();
    __half* dst = vT + (size_t)bh * DH * SEQ;
    #pragma unroll
    for (int t = 0; t < 4; t++)
        dst[(size_t)(d0 + ty + t * 8) * SEQ + j0 + tx] = tile[tx][ty + t * 8];
}

// ---------------------------------------------------------------------------
// fp16 tensor-core GEMM (fp32 accum), register-staged prefetch, ldmatrix
// fragment loads (conflict-free at LK=40).
// MODE 0: QKV (A fp32)   MODE 1: OUT (+bias, C fp32)
// MODE 2: AV (per bh, C fp16)   MODE 3: DOTS (per bh, alpha, C fp32)
// ---------------------------------------------------------------------------
template<int MODE, int BM, int BN, int KTOT>
__global__ void __launch_bounds__(256) hgemm(
    const void* __restrict__ gA, const void* __restrict__ gB,
    const float* __restrict__ bias, void* __restrict__ gC)
{
    constexpr bool AHALF = (MODE != 0);
    constexpr bool CHALF = (MODE == 0 || MODE == 2);
    constexpr int MI = BM / 64;          // m16 tiles per warp
    constexpr int NP = BN / 32;          // n16 ldmatrix pairs per warp
    constexpr int LK = 40;
    constexpr int NLDA_F = BM / 32;
    constexpr int NLDA_H = BM / 64;
    constexpr int NLDB_H = BN / 64;

    __shared__ __align__(16) __half sA[BM * LK];
    __shared__ __align__(16) __half sB[BN * LK];

    const int tid  = threadIdx.x;
    const int row0 = blockIdx.y * BM;
    const int col0 = blockIdx.x * BN;

    const float*  Af = nullptr;
    const __half* Ah = nullptr;
    const __half* Bh = nullptr;
    float*  Cf = nullptr;
    __half* Ch = nullptr;
    size_t lda, ldb, ldc;
    float alpha = 1.0f;

    if (MODE == 0) {
        Af = (const float*)gA;  lda = DMODEL;
        Bh = (const __half*)gB; ldb = DMODEL;
        Ch = (__half*)gC;       ldc = QKV_N;
    } else if (MODE == 1) {
        Ah = (const __half*)gA; lda = DMODEL;
        Bh = (const __half*)gB; ldb = DMODEL;
        Cf = (float*)gC;        ldc = DMODEL;
    } else if (MODE == 2) {
        const int bh = blockIdx.z, b = bh >> 4, h = bh & 15;
        Ah = (const __half*)gA + (size_t)bh * SEQ * SEQ;          lda = SEQ;
        Bh = (const __half*)gB + (size_t)bh * DH * SEQ;           ldb = SEQ;
        Ch = (__half*)gC + (size_t)b * SEQ * INNER + (size_t)h * DH; ldc = INNER;
    } else {
        const int bh = blockIdx.z, b = bh >> 4, h = bh & 15;
        Ah = (const __half*)gA + (size_t)b * SEQ * QKV_N + (size_t)h * DH;
        lda = QKV_N;
        Bh = (const __half*)gB + (size_t)b * SEQ * QKV_N + INNER + (size_t)h * DH;
        ldb = QKV_N;
        Cf = (float*)gC + (size_t)bh * SEQ * SEQ;                 ldc = SEQ;
        alpha = 0.125f;
    }

    const int warp = tid >> 5, lane = tid & 31;
    const int wm = warp >> 1, wn = warp & 1;
    const int g = lane >> 2, t4 = lane & 3;

    // ldmatrix per-lane row/col-half selectors
    const int lmRow = lane & 15;         // row within 16-row span
    const int lmK8  = (lane >> 4) * 8;   // k offset 0 or 8

    const int aR  = tid >> 3;            // fp32 staging row base
    const int aC4 = tid & 7;
    const int hR  = tid >> 2;            // half staging row base
    const int hC  = tid & 3;

    float4 raf[NLDA_F];
    uint4  rah[NLDA_H];
    uint4  rbh[NLDB_H];

    auto loadA = [&](int k0) {
        if (AHALF) {
            #pragma unroll
            for (int p = 0; p < NLDA_H; p++) {
                int r = hR + p * 64;
                rah[p] = *reinterpret_cast<const uint4*>(
                    &Ah[(size_t)(row0 + r) * lda + k0 + hC * 8]);
            }
        } else {
            #pragma unroll
            for (int t = 0; t < NLDA_F; t++) {
                int r = aR + t * 32;
                raf[t] = *reinterpret_cast<const float4*>(
                    &Af[(size_t)(row0 + r) * lda + k0 + aC4 * 4]);
            }
        }
    };
    auto stsA = [&]() {
        if (AHALF) {
            #pragma unroll
            for (int p = 0; p < NLDA_H; p++) {
                int r = hR + p * 64;
                *reinterpret_cast<uint4*>(&sA[(size_t)r * LK + hC * 8]) = rah[p];
            }
        } else {
            #pragma unroll
            for (int t = 0; t < NLDA_F; t++) {
                int r = aR + t * 32;
                __half2 h01 = __floats2half2_rn(raf[t].x, raf[t].y);
                __half2 h23 = __floats2half2_rn(raf[t].z, raf[t].w);
                uint2 u;
                u.x = *reinterpret_cast<uint32_t*>(&h01);
                u.y = *reinterpret_cast<uint32_t*>(&h23);
                *reinterpret_cast<uint2*>(&sA[(size_t)r * LK + aC4 * 4]) = u;
            }
        }
    };
    auto loadB = [&](int k0) {
        #pragma unroll
        for (int p = 0; p < NLDB_H; p++) {
            int r = hR + p * 64;
            rbh[p] = *reinterpret_cast<const uint4*>(
                &Bh[(size_t)(col0 + r) * ldb + k0 + hC * 8]);
        }
    };
    auto stsB = [&]() {
        #pragma unroll
        for (int p = 0; p < NLDB_H; p++) {
            int r = hR + p * 64;
            *reinterpret_cast<uint4*>(&sB[(size_t)r * LK + hC * 8]) = rbh[p];
        }
    };

    float acc[MI][NP * 2][4] = {};

    loadA(0); loadB(0);
    stsA(); stsB();
    __syncthreads();

    for (int k0 = 0; k0 < KTOT; k0 += 32) {
        const bool more = (k0 + 32 < KTOT);
        if (more) { loadA(k0 + 32); loadB(k0 + 32); }

        #pragma unroll
        for (int kk = 0; kk < 2; kk++) {
            const int kc = kk * 16 + lmK8;
            uint32_t af[MI][4];
            #pragma unroll
            for (int mi = 0; mi < MI; mi++) {
                int r = wm * (BM / 4) + mi * 16 + lmRow;
                ldsm_x4(af[mi], &sA[(size_t)r * LK + kc]);
            }
            uint32_t bfp[NP][4];
            #pragma unroll
            for (int p = 0; p < NP; p++) {
                int c = wn * (BN / 2) + p * 16 + lmRow;
                ldsm_x4(bfp[p], &sB[(size_t)c * LK + kc]);
            }
            #pragma unroll
            for (int mi = 0; mi < MI; mi++)
                #pragma unroll
                for (int p = 0; p < NP; p++) {
                    uint32_t b0[2] = { bfp[p][0], bfp[p][2] };
                    uint32_t b1[2] = { bfp[p][1], bfp[p][3] };
                    mma16(acc[mi][2 * p],     af[mi], b0);
                    mma16(acc[mi][2 * p + 1], af[mi], b1);
                }
        }

        if (more) {
            __syncthreads();
            stsA(); stsB();
            __syncthreads();
        }
    }

    // Epilogue
    #pragma unroll
    for (int mi = 0; mi < MI; mi++) {
        int r = row0 + wm * (BM / 4) + mi * 16 + g;
        #pragma unroll
        for (int ni = 0; ni < NP * 2; ni++) {
            int c = col0 + wn * (BN / 2) + (ni >> 1) * 16 + (ni & 1) * 8 + 2 * t4;
            float* a = acc[mi][ni];
            if (CHALF) {
                __half2 hv0 = __floats2half2_rn(a[0], a[1]);
                __half2 hv1 = __floats2half2_rn(a[2], a[3]);
                *reinterpret_cast<__half2*>(&Ch[(size_t)r * ldc + c]) = hv0;
                *reinterpret_cast<__half2*>(&Ch[(size_t)(r + 8) * ldc + c]) = hv1;
            } else {
                float b0 = 0.f, b1 = 0.f;
                if (MODE == 1) { b0 = bias[c]; b1 = bias[c + 1]; }
                float2 v0, v1;
                v0.x = a[0] * alpha + b0; v0.y = a[1] * alpha + b1;
                v1.x = a[2] * alpha + b0; v1.y = a[3] * alpha + b1;
                *reinterpret_cast<float2*>(&Cf[(size_t)r * ldc + c]) = v0;
                *reinterpret_cast<float2*>(&Cf[(size_t)(r + 8) * ldc + c]) = v1;
            }
        }
    }
}

// ---------------------------------------------------------------------------
// Fused softmax + head-mix + LayerNorm: 512 threads (one warp per head for
// softmax, one j per thread for mix/LN). No min-blocks clause -> no reg cap.
// ---------------------------------------------------------------------------
__global__ void __launch_bounds__(512) softmax_mix_ln_kernel(
    const float* __restrict__ dots, __half* __restrict__ attnh,
    const float* __restrict__ W,
    const float* __restrict__ gamma, const float* __restrict__ beta)
{
    const int bi = blockIdx.x;
    const int b  = bi >> 9;
    const int i  = bi & 511;

    __shared__ float sc[HEADS][SEQ];
    __shared__ float wmat[HEADS][HEADS];
    __shared__ float sg[HEADS], sb[HEADS];

    const int tid = threadIdx.x;
    if (tid < 256) wmat[tid >> 4][tid & 15] = W[tid];
    if (tid < HEADS) { sg[tid] = gamma[tid]; sb[tid] = beta[tid]; }

    #pragma unroll
    for (int t = 0; t < 4; t++) {
        int idx = tid + t * 512;
        int h   = idx >> 7;
        int j4  = idx & 127;
        float4 v = *reinterpret_cast<const float4*>(
            &dots[((size_t)(b * HEADS + h) * SEQ + i) * SEQ + j4 * 4]);
        *reinterpret_cast<float4*>(&sc[h][j4 * 4]) = v;
    }
    __syncthreads();

    const int h = tid >> 5, lane = tid & 31;
    {
        float mx = -1e30f;
        #pragma unroll
        for (int t = 0; t < 16; t++) mx = fmaxf(mx, sc[h][lane + t * 32]);
        #pragma unroll
        for (int o = 16; o > 0; o >>= 1)
            mx = fmaxf(mx, __shfl_xor_sync(0xffffffffu, mx, o));
        float s = 0.f;
        #pragma unroll
        for (int t = 0; t < 16; t++) {
            float e = __expf(sc[h][lane + t * 32] - mx);
            sc[h][lane + t * 32] = e;
            s += e;
        }
        #pragma unroll
        for (int o = 16; o > 0; o >>= 1)
            s += __shfl_xor_sync(0xffffffffu, s, o);
        float inv = 1.f / s;
        #pragma unroll
        for (int t = 0; t < 16; t++) sc[h][lane + t * 32] *= inv;
    }
    __syncthreads();

    {
        const int j = tid;
        float a[HEADS];
        #pragma unroll
        for (int hh = 0; hh < HEADS; hh++) a[hh] = sc[hh][j];
        float mixed[HEADS];
        #pragma unroll
        for (int gg = 0; gg < HEADS; gg++) {
            float s = 0.f;
            #pragma unroll
            for (int hh = 0; hh < HEADS; hh++) s = fmaf(a[hh], wmat[hh][gg], s);
            mixed[gg] = s;
        }
        float mean = 0.f;
        #pragma unroll
        for (int gg = 0; gg < HEADS; gg++) mean += mixed[gg];
        mean *= (1.f / HEADS);
        float var = 0.f;
        #pragma unroll
        for (int gg = 0; gg < HEADS; gg++) {
            float d = mixed[gg] - mean;
            var = fmaf(d, d, var);
        }
        var *= (1.f / HEADS);
        float inv = rsqrtf(var + 1e-3f);
        #pragma unroll
        for (int gg = 0; gg < HEADS; gg++) {
            float y = (mixed[gg] - mean) * inv * sg[gg] + sb[gg];
            attnh[((size_t)(b * HEADS + gg) * SEQ + i) * SEQ + j] =
                __float2half_rn(y);
        }
    }
}

// ---------------------------------------------------------------------------
extern "C" void kernel_launch(void* const* d_in, const int* in_sizes, int n_in,
                              void* d_out, int out_size)
{
    const float* x        = (const float*)d_in[0];
    const float* w_qkv    = (const float*)d_in[1];
    const float* reattn_w = (const float*)d_in[2];
    const float* ln_gamma = (const float*)d_in[3];
    const float* ln_beta  = (const float*)d_in[4];
    const float* w_out    = (const float*)d_in[5];
    const float* b_out    = (const float*)d_in[6];
    float* out = (float*)d_out;

    __half *qkvh = nullptr, *attnh = nullptr, *avh = nullptr;
    __half *wqkvT = nullptr, *woutT = nullptr, *vT = nullptr;
    float *dots = nullptr;
    cudaGetSymbolAddress((void**)&qkvh,  g_qkvh);
    cudaGetSymbolAddress((void**)&dots,  g_dots);
    cudaGetSymbolAddress((void**)&attnh, g_attnh);
    cudaGetSymbolAddress((void**)&avh,   g_avh);
    cudaGetSymbolAddress((void**)&wqkvT, g_wqkvT);
    cudaGetSymbolAddress((void**)&woutT, g_woutT);
    cudaGetSymbolAddress((void**)&vT,    g_vT);

    dim3 blk(256);

    // 0) weight prep
    transpose_cvt<<<dim3(QKV_N / 32, DMODEL / 32), blk>>>(w_qkv, wqkvT, DMODEL, QKV_N);
    transpose_cvt<<<dim3(DMODEL / 32, DMODEL / 32), blk>>>(w_out, woutT, DMODEL, DMODEL);

    // 1) QKV projection -> fp16
    hgemm<0, 128, 128, 1024><<<dim3(QKV_N / 128, NTOK / 128), blk>>>(
        x, wqkvT, nullptr, qkvh);

    // 1b) V transpose
    v_transpose<<<dim3(SEQ / 32, DH / 32, BATCH * HEADS), blk>>>(qkvh, vT);

    // 2) dots -> fp32
    hgemm<3, 128, 128, 64><<<dim3(SEQ / 128, SEQ / 128, BATCH * HEADS), blk>>>(
        qkvh, qkvh, nullptr, dots);

    // 3) fused softmax + head mix + LayerNorm -> fp16
    softmax_mix_ln_kernel<<<BATCH * SEQ, 512>>>(dots, attnh, reattn_w, ln_gamma, ln_beta);

    // 4) AV -> fp16
    hgemm<2, 128, 64, 512><<<dim3(1, SEQ / 128, BATCH * HEADS), blk>>>(
        attnh, vT, nullptr, avh);

    // 5) output projection + bias -> fp32
    hgemm<1, 128, 128, 1024><<<dim3(DMODEL / 128, NTOK / 128), blk>>>(
        avh, woutT, b_out, out);
}